// round 7
// baseline (speedup 1.0000x reference)
#include <cuda_runtime.h>
#include <cuda_bf16.h>
#include <math.h>

#define BB   16
#define TT   256
#define HH   512
#define VV   32000
#define G4   2048
#define SS   257
#define NROW (BB*TT)

// ---------------- static device scratch (allocation-free) ----------------
__device__ float g_seq  [NROW*HH];
__device__ float g_X0   [NROW*G4];
__device__ float g_hout [NROW*HH];
__device__ float g_h0T  [BB*HH];
__device__ float g_h1T  [BB*HH];
__device__ float g_c0   [BB*HH];
__device__ float g_c1   [BB*HH];
__device__ float g_gate0[BB*G4];
__device__ float g_gate1[BB*G4];
__device__ float g_scores[(size_t)BB*TT*TT];
__device__ float g_attw  [(size_t)BB*TT*TT];
__device__ float g_ctx  [NROW*HH];
__device__ float g_pred [NROW*HH];
__device__ unsigned g_barC;   // arrival count (returns to 0)
__device__ unsigned g_barG;   // generation (monotonic -> graph-replay safe)

// ---------------- grid barrier ----------------
__device__ __forceinline__ void grid_barrier() {
    __syncthreads();
    if (threadIdx.x == 0) {
        __threadfence();
        volatile unsigned* vg = &g_barG;
        unsigned cur = *vg;
        unsigned t = atomicAdd(&g_barC, 1u);
        if (t == gridDim.x - 1u) {
            g_barC = 0u;
            __threadfence();
            *vg = cur + 1u;
        } else {
            while (*vg == cur) { }
            __threadfence();
        }
    }
    __syncthreads();
}

// ---------------- embedding gather ----------------
__global__ void k_gather(const int* __restrict__ tok, const float* __restrict__ emb,
                         float* __restrict__ seq) {
    int row = blockIdx.x;                      // b*256 + t
    int b = row >> 8, t = row & 255;
    int tk = tok[b*SS + t];                    // inp = tok_seq[:, :-1]
    const float4* s = (const float4*)(emb + (size_t)tk*HH);
    float4* d = (float4*)(seq + (size_t)row*HH);
    d[threadIdx.x] = s[threadIdx.x];           // 128 thr * float4 = 512
}

// ---------------- generic SGEMM: C = act(A@B + bias), optional batch ----------------
// BM=BN=128, BK=8, 256 threads, 8x8 per thread. All dims divide tiles exactly.
template<int ACAT, int DOTANH>
__global__ void __launch_bounds__(256) k_sgemm(
    const float* __restrict__ A, const float* __restrict__ A2,
    const float* __restrict__ Bm, const float* __restrict__ bias,
    float* __restrict__ C, int M, int N, int K,
    long long sA, long long sB, long long sC)
{
    __shared__ __align__(16) float As[8][128];
    __shared__ __align__(16) float Bs[8][128];
    A  += (long long)blockIdx.z * sA;
    Bm += (long long)blockIdx.z * sB;
    C  += (long long)blockIdx.z * sC;
    const int tid = threadIdx.x;
    const int m0 = blockIdx.y * 128, n0 = blockIdx.x * 128;
    const int ar = tid >> 1,  ac = (tid & 1) * 4;
    const int br = tid >> 5,  bc = (tid & 31) * 4;
    const int tx = tid & 15,  ty = tid >> 4;

    float acc[8][8];
#pragma unroll
    for (int i = 0; i < 8; i++)
#pragma unroll
        for (int j = 0; j < 8; j++) acc[i][j] = 0.f;

    for (int k0 = 0; k0 < K; k0 += 8) {
        float4 av;
        if (ACAT) {   // A = [A | A2] along K, each half lda = 512
            int kk = k0 + ac;
            const float* src = (kk < 512) ? (A  + (size_t)(m0+ar)*512 + kk)
                                          : (A2 + (size_t)(m0+ar)*512 + (kk-512));
            av = *(const float4*)src;
        } else {
            av = *(const float4*)(A + (size_t)(m0+ar)*K + (k0+ac));
        }
        float4 bv = *(const float4*)(Bm + (size_t)(k0+br)*N + (n0+bc));
        __syncthreads();
        As[ac+0][ar] = av.x; As[ac+1][ar] = av.y;
        As[ac+2][ar] = av.z; As[ac+3][ar] = av.w;
        *(float4*)&Bs[br][bc] = bv;
        __syncthreads();
#pragma unroll
        for (int k = 0; k < 8; k++) {
            float ra[8], rb[8];
            *(float4*)&ra[0] = *(const float4*)&As[k][ty*8];
            *(float4*)&ra[4] = *(const float4*)&As[k][ty*8+4];
            *(float4*)&rb[0] = *(const float4*)&Bs[k][tx*8];
            *(float4*)&rb[4] = *(const float4*)&Bs[k][tx*8+4];
#pragma unroll
            for (int i = 0; i < 8; i++)
#pragma unroll
                for (int j = 0; j < 8; j++) acc[i][j] += ra[i]*rb[j];
        }
    }
#pragma unroll
    for (int i = 0; i < 8; i++) {
        float* cp = C + (size_t)(m0 + ty*8 + i)*N + n0 + tx*8;
        float v[8];
#pragma unroll
        for (int j = 0; j < 8; j++) {
            float x = acc[i][j];
            if (bias) x += bias[n0 + tx*8 + j];
            if (DOTANH) x = tanhf(x);
            v[j] = x;
        }
        *(float4*)(cp+0) = make_float4(v[0],v[1],v[2],v[3]);
        *(float4*)(cp+4) = make_float4(v[4],v[5],v[6],v[7]);
    }
}

// ---------------- persistent LSTM ----------------
__device__ __forceinline__ float sigf(float x){ return 1.f/(1.f+expf(-x)); }

// gout[b][col] = bias + addv + sum_k x[k][b]*W[k][col]; 16 cols per block.
// 256 thr = 16 cols x 16 k-chunks, 16 batch accumulators each.
__device__ __forceinline__ void lstm_gemm(
    const float* __restrict__ W0, const float* __restrict__ W1,   // rows [0,512)/[512,K)
    const float* __restrict__ x0T, const float* __restrict__ x1T, // [k][16]
    const float* __restrict__ addv, int addstride,
    const float* __restrict__ bias,
    float* __restrict__ gout, int K, float* red)
{
    const int tid = threadIdx.x;
    const int cl = tid & 15, kc = tid >> 4;
    const int col = blockIdx.x * 16 + cl;
    const int CH  = K >> 4;                   // 32 or 64; chunk never straddles 512
    const int k0  = kc * CH;
    const float* Wb = ((k0 < 512) ? (W0 + (size_t)k0*G4)
                                  : (W1 + (size_t)(k0-512)*G4)) + col;
    const float* xb = (k0 < 512) ? (x0T + k0*BB) : (x1T + (k0-512)*BB);

    float acc[16];
#pragma unroll
    for (int b = 0; b < 16; b++) acc[b] = 0.f;

#pragma unroll 8
    for (int kk = 0; kk < CH; ++kk) {
        float w = Wb[(size_t)kk*G4];                          // L1-resident weights
        float4 xa = __ldcg((const float4*)(xb + kk*BB + 0));  // cross-block: L2
        float4 xc = __ldcg((const float4*)(xb + kk*BB + 4));
        float4 xe = __ldcg((const float4*)(xb + kk*BB + 8));
        float4 xg = __ldcg((const float4*)(xb + kk*BB + 12));
        acc[0]  += w*xa.x; acc[1]  += w*xa.y; acc[2]  += w*xa.z; acc[3]  += w*xa.w;
        acc[4]  += w*xc.x; acc[5]  += w*xc.y; acc[6]  += w*xc.z; acc[7]  += w*xc.w;
        acc[8]  += w*xe.x; acc[9]  += w*xe.y; acc[10] += w*xe.z; acc[11] += w*xe.w;
        acc[12] += w*xg.x; acc[13] += w*xg.y; acc[14] += w*xg.z; acc[15] += w*xg.w;
    }
    float* r = red + cl*260 + kc*16;          // stride 260 staggers banks
    *(float4*)(r+0)  = make_float4(acc[0], acc[1], acc[2], acc[3]);
    *(float4*)(r+4)  = make_float4(acc[4], acc[5], acc[6], acc[7]);
    *(float4*)(r+8)  = make_float4(acc[8], acc[9], acc[10],acc[11]);
    *(float4*)(r+12) = make_float4(acc[12],acc[13],acc[14],acc[15]);
    __syncthreads();
    {
        const int ob = tid >> 4, ocl = tid & 15;
        float s = 0.f;
#pragma unroll
        for (int q = 0; q < 16; q++) s += red[ocl*260 + q*16 + ob];
        const int ocol = blockIdx.x*16 + ocl;
        if (bias) s += bias[ocol];
        if (addv) s += addv[(size_t)ob*addstride + ocol];
        gout[ob*G4 + ocol] = s;
    }
    __syncthreads();   // red reusable by next call
}

__device__ __forceinline__ void lstm_cell(
    const float* __restrict__ g, float* __restrict__ c,
    float* __restrict__ hT, float* __restrict__ hout, int t)
{
    int gid = blockIdx.x * blockDim.x + threadIdx.x;
    if (gid < BB*HH) {
        int b = gid >> 9, j = gid & 511;
        const float* gb = g + b*G4;
        float gi = __ldcg(gb + j);
        float gf = __ldcg(gb + 512  + j);
        float gg = __ldcg(gb + 1024 + j);
        float go = __ldcg(gb + 1536 + j);
        float cc = __ldcg(c + b*HH + j);
        float cn = sigf(gf)*cc + sigf(gi)*tanhf(gg);
        float hn = sigf(go)*tanhf(cn);
        c[b*HH + j] = cn;
        hT[j*BB + b] = hn;
        if (hout) hout[(size_t)(b*TT + t)*HH + j] = hn;
    }
}

__global__ void __launch_bounds__(256, 1) k_lstm(
    const float* __restrict__ Whh0, const float* __restrict__ Wih1,
    const float* __restrict__ Whh1, const float* __restrict__ b1)
{
    __shared__ __align__(16) float red[16*260];
    int gid = blockIdx.x*256 + threadIdx.x;
    for (int i = gid; i < BB*HH; i += gridDim.x*blockDim.x) {
        g_h0T[i] = 0.f; g_h1T[i] = 0.f; g_c0[i] = 0.f; g_c1[i] = 0.f;
    }
    grid_barrier();
    for (int t = 0; t < TT; ++t) {
        // layer0: g0 = X0[:,t,:] + h0@Whh0   (x@Wih0+b0 pre-folded into X0)
        lstm_gemm(Whh0, nullptr, g_h0T, nullptr,
                  g_X0 + (size_t)t*G4, TT*G4, nullptr, g_gate0, 512, red);
        grid_barrier();
        lstm_cell(g_gate0, g_c0, g_h0T, nullptr, t);
        grid_barrier();
        // layer1: g1 = h0@Wih1 + h1@Whh1 + b1   (concat K=1024)
        lstm_gemm(Wih1, Whh1, g_h0T, g_h1T, nullptr, 0, b1, g_gate1, 1024, red);
        grid_barrier();
        lstm_cell(g_gate1, g_c1, g_h1T, g_hout, t);
        // cell1's writes are disjoint from gemm0(t+1); 2 barriers before gemm1(t+1)
    }
}

// ---------------- attention: scores_b = out_b @ out_b^T ----------------
__global__ void __launch_bounds__(256) k_scores(const float* __restrict__ out) {
    __shared__ __align__(16) float As[16][64];
    __shared__ __align__(16) float Bs[16][64];
    const int b = blockIdx.z;
    const float* A = out + (size_t)b*TT*HH;
    const int m0 = blockIdx.y*64, n0 = blockIdx.x*64;
    const int tid = threadIdx.x;
    const int lr = tid >> 2, lk = (tid & 3)*4;
    const int tx = tid & 15, ty = tid >> 4;
    float acc[4][4];
#pragma unroll
    for (int i=0;i<4;i++)
#pragma unroll
        for (int j=0;j<4;j++) acc[i][j]=0.f;

    for (int k0 = 0; k0 < HH; k0 += 16) {
        float4 av = *(const float4*)(A + (size_t)(m0+lr)*HH + k0+lk);
        float4 bv = *(const float4*)(A + (size_t)(n0+lr)*HH + k0+lk);
        __syncthreads();
        As[lk+0][lr]=av.x; As[lk+1][lr]=av.y; As[lk+2][lr]=av.z; As[lk+3][lr]=av.w;
        Bs[lk+0][lr]=bv.x; Bs[lk+1][lr]=bv.y; Bs[lk+2][lr]=bv.z; Bs[lk+3][lr]=bv.w;
        __syncthreads();
#pragma unroll
        for (int k = 0; k < 16; k++) {
            float4 ra = *(const float4*)&As[k][ty*4];
            float4 rb = *(const float4*)&Bs[k][tx*4];
            float a4[4]={ra.x,ra.y,ra.z,ra.w};
            float b4[4]={rb.x,rb.y,rb.z,rb.w};
#pragma unroll
            for (int i=0;i<4;i++)
#pragma unroll
                for (int j=0;j<4;j++) acc[i][j] += a4[i]*b4[j];
        }
    }
#pragma unroll
    for (int i = 0; i < 4; i++)
        *(float4*)(g_scores + (size_t)b*TT*TT + (size_t)(m0+ty*4+i)*TT + n0 + tx*4)
            = make_float4(acc[i][0],acc[i][1],acc[i][2],acc[i][3]);
}

// softmax over axis=1 using symmetry: attw[b][j][i] = w[b][i][j]
__global__ void k_softmax(const int* __restrict__ tok) {
    const int b = blockIdx.y, j = blockIdx.x, i = threadIdx.x;
    const float* row = g_scores + ((size_t)b*TT + j)*TT;
    const bool m = tok[b*SS + i + 1] != 0;         // tgt = tok_seq[:,1:]
    float s = m ? row[i] : -1e9f;
    __shared__ float sh[8];
    float v = s;
#pragma unroll
    for (int o = 16; o; o >>= 1) v = fmaxf(v, __shfl_xor_sync(~0u, v, o));
    if ((i & 31) == 0) sh[i >> 5] = v;
    __syncthreads();
    float mx = sh[0];
#pragma unroll
    for (int q = 1; q < 8; q++) mx = fmaxf(mx, sh[q]);
    float e = expf(s - mx);
    float t2 = e;
#pragma unroll
    for (int o = 16; o; o >>= 1) t2 += __shfl_xor_sync(~0u, t2, o);
    __syncthreads();
    if ((i & 31) == 0) sh[i >> 5] = t2;
    __syncthreads();
    float sum = 0.f;
#pragma unroll
    for (int q = 0; q < 8; q++) sum += sh[q];
    g_attw[((size_t)b*TT + j)*TT + i] = m ? (e/sum) : 0.f;
}

// ---------------- launch ----------------
extern "C" void kernel_launch(void* const* d_in, const int* in_sizes, int n_in,
                              void* d_out, int out_size) {
    const int*   tok  = (const int*)  d_in[0];
    const float* emb  = (const float*)d_in[1];
    const float* Wih0 = (const float*)d_in[2];
    const float* Whh0 = (const float*)d_in[3];
    const float* b0   = (const float*)d_in[4];
    const float* Wih1 = (const float*)d_in[5];
    const float* Whh1 = (const float*)d_in[6];
    const float* b1   = (const float*)d_in[7];
    const float* Wc   = (const float*)d_in[8];
    const float* bc   = (const float*)d_in[9];
    const float* Wp   = (const float*)d_in[10];
    const float* bp   = (const float*)d_in[11];
    float* logits = (float*)d_out;

    void *p_seq, *p_X0, *p_hout, *p_attw, *p_ctx, *p_pred;
    cudaGetSymbolAddress(&p_seq,  g_seq);
    cudaGetSymbolAddress(&p_X0,   g_X0);
    cudaGetSymbolAddress(&p_hout, g_hout);
    cudaGetSymbolAddress(&p_attw, g_attw);
    cudaGetSymbolAddress(&p_ctx,  g_ctx);
    cudaGetSymbolAddress(&p_pred, g_pred);
    float* seq  = (float*)p_seq;   float* X0   = (float*)p_X0;
    float* hout = (float*)p_hout;  float* attw = (float*)p_attw;
    float* ctx  = (float*)p_ctx;   float* pred = (float*)p_pred;

    // 1. embedding gather
    k_gather<<<NROW, 128>>>(tok, emb, seq);
    // 2. X0 = seq @ Wih0 + b0   [4096 x 2048]
    k_sgemm<0,0><<<dim3(G4/128, NROW/128, 1), 256>>>(
        seq, nullptr, Wih0, b0, X0, NROW, G4, HH, 0, 0, 0);
    // 3. persistent 2-layer LSTM (128 co-resident CTAs)
    k_lstm<<<128, 256>>>(Whh0, Wih1, Whh1, b1);
    // 4. scores_b = out_b @ out_b^T
    k_scores<<<dim3(TT/64, TT/64, BB), 256>>>(hout);
    // 5. masked softmax (axis=1 via symmetry) -> attw = w^T
    k_softmax<<<dim3(TT, BB, 1), TT>>>(tok);
    // 6. ctx_b = attw_b @ out_b   (batched)
    k_sgemm<0,0><<<dim3(HH/128, TT/128, BB), 256>>>(
        attw, nullptr, hout, nullptr, ctx, TT, HH, TT,
        (long long)TT*TT, (long long)TT*HH, (long long)TT*HH);
    // 7. pred = tanh([ctx | out] @ Wc + bc)
    k_sgemm<1,1><<<dim3(HH/128, NROW/128, 1), 256>>>(
        ctx, hout, Wc, bc, pred, NROW, HH, 2*HH, 0, 0, 0);
    // 8. logits = pred @ Wp + bp   [4096 x 32000]
    k_sgemm<0,0><<<dim3(VV/128, NROW/128, 1), 256>>>(
        pred, nullptr, Wp, bp, logits, NROW, VV, HH, 0, 0, 0);
}

// round 8
// speedup vs baseline: 1.2423x; 1.2423x over previous
#include <cuda_runtime.h>
#include <cuda_bf16.h>
#include <math.h>
#include <stdint.h>

#define BB   16
#define TT   256
#define HH   512
#define VV   32000
#define G4   2048
#define SS   257
#define NROW (BB*TT)
#define KS   1536           // split K' = 3*512

// ---------------- static device scratch (allocation-free) ----------------
__device__ float g_seq  [NROW*HH];
__device__ float g_X0   [NROW*G4];
__device__ float g_hout [NROW*HH];
__device__ float g_h0T  [BB*HH];
__device__ float g_h1T  [BB*HH];
__device__ float g_c0   [BB*HH];
__device__ float g_c1   [BB*HH];
__device__ float g_gate0[BB*G4];
__device__ float g_gate1[BB*G4];
__device__ float g_scores[(size_t)BB*TT*TT];
__device__ float g_attw  [(size_t)BB*TT*TT];
__device__ float g_ctx  [NROW*HH];
__device__ float g_pred [NROW*HH];
__device__ __nv_bfloat16 g_Abf[(size_t)NROW*KS];     // split A (seq, then pred)
__device__ __nv_bfloat16 g_Bbf[(size_t)KS*VV];       // split B (Wih0, then Wp)
__device__ unsigned g_barC;   // arrival count (returns to 0)
__device__ unsigned g_barG;   // generation (monotonic -> graph-replay safe)

// ---------------- grid barrier ----------------
__device__ __forceinline__ void grid_barrier() {
    __syncthreads();
    if (threadIdx.x == 0) {
        __threadfence();
        volatile unsigned* vg = &g_barG;
        unsigned cur = *vg;
        unsigned t = atomicAdd(&g_barC, 1u);
        if (t == gridDim.x - 1u) {
            g_barC = 0u;
            __threadfence();
            *vg = cur + 1u;
        } else {
            while (*vg == cur) { }
            __threadfence();
        }
    }
    __syncthreads();
}

// ---------------- embedding gather ----------------
__global__ void k_gather(const int* __restrict__ tok, const float* __restrict__ emb,
                         float* __restrict__ seq) {
    int row = blockIdx.x;                      // b*256 + t
    int b = row >> 8, t = row & 255;
    int tk = tok[b*SS + t];                    // inp = tok_seq[:, :-1]
    const float4* s = (const float4*)(emb + (size_t)tk*HH);
    float4* d = (float4*)(seq + (size_t)row*HH);
    d[threadIdx.x] = s[threadIdx.x];           // 128 thr * float4 = 512
}

// ---------------- bf16 split conversion ----------------
// A-side: src [M x 512] fp32 -> dst [M x 1536] bf16 as [hi | hi | lo]
__global__ void k_cvtA(const float* __restrict__ src, __nv_bfloat16* __restrict__ dst) {
    int idx = blockIdx.x*256 + threadIdx.x;        // one float4 per thread
    int r = idx >> 7, c = (idx & 127) * 4;         // K=512 -> 128 float4/row
    float4 v = *(const float4*)(src + (size_t)r*512 + c);
    float vv[4] = {v.x, v.y, v.z, v.w};
    __align__(8) __nv_bfloat16 hi[4], lo[4];
#pragma unroll
    for (int i = 0; i < 4; i++) {
        hi[i] = __float2bfloat16(vv[i]);
        lo[i] = __float2bfloat16(vv[i] - __bfloat162float(hi[i]));
    }
    __nv_bfloat16* base = dst + (size_t)r*KS;
    *(uint2*)(base + c)        = *(uint2*)hi;
    *(uint2*)(base + 512 + c)  = *(uint2*)hi;
    *(uint2*)(base + 1024 + c) = *(uint2*)lo;
}

// B-side: src [512 x N] fp32 -> dst [1536 x N] bf16: row k = hi, 512+k = lo, 1024+k = hi
__global__ void k_cvtB(const float* __restrict__ src, __nv_bfloat16* __restrict__ dst, int N) {
    int idx = blockIdx.x*256 + threadIdx.x;
    int n4 = N >> 2;
    int k = idx / n4, n = (idx % n4) * 4;
    float4 v = *(const float4*)(src + (size_t)k*N + n);
    float vv[4] = {v.x, v.y, v.z, v.w};
    __align__(8) __nv_bfloat16 hi[4], lo[4];
#pragma unroll
    for (int i = 0; i < 4; i++) {
        hi[i] = __float2bfloat16(vv[i]);
        lo[i] = __float2bfloat16(vv[i] - __bfloat162float(hi[i]));
    }
    *(uint2*)(dst + (size_t)k*N + n)          = *(uint2*)hi;
    *(uint2*)(dst + (size_t)(512 + k)*N + n)  = *(uint2*)lo;
    *(uint2*)(dst + (size_t)(1024 + k)*N + n) = *(uint2*)hi;
}

// ---------------- bf16 HMMA GEMM: C = A'@B' + bias (fp32 out) ----------------
__device__ __forceinline__ uint32_t s2u(const void* p) {
    return (uint32_t)__cvta_generic_to_shared(p);
}
__device__ __forceinline__ void cpa16(uint32_t s, const void* g) {
    asm volatile("cp.async.cg.shared.global [%0], [%1], 16;" :: "r"(s), "l"(g));
}
__device__ __forceinline__ void mma16816(float* d, const uint32_t* a, const uint32_t* b) {
    asm volatile(
        "mma.sync.aligned.m16n8k16.row.col.f32.bf16.bf16.f32 "
        "{%0,%1,%2,%3}, {%4,%5,%6,%7}, {%8,%9}, {%0,%1,%2,%3};"
        : "+f"(d[0]), "+f"(d[1]), "+f"(d[2]), "+f"(d[3])
        : "r"(a[0]), "r"(a[1]), "r"(a[2]), "r"(a[3]), "r"(b[0]), "r"(b[1]));
}

// Tiles: 128(M) x 128(N), K-step 32, 256 thr = 8 warps of 64x32.
// As stride 40 bf16 (80B), Bs stride 136 bf16 (272B): conflict-free LDSM.
__global__ void __launch_bounds__(256) k_hgemm(
    const __nv_bfloat16* __restrict__ A, const __nv_bfloat16* __restrict__ Bm,
    const float* __restrict__ bias, float* __restrict__ C,
    int M, int N, int K)
{
    __shared__ __align__(16) __nv_bfloat16 As[2][128*40];
    __shared__ __align__(16) __nv_bfloat16 Bs[2][32*136];
    const int tid  = threadIdx.x;
    const int lane = tid & 31;
    const int wid  = tid >> 5;
    const int m0 = blockIdx.y * 128, n0 = blockIdx.x * 128;
    const int wm0 = (wid >> 2) * 64;      // warp row {0,64}
    const int wn0 = (wid & 3) * 32;       // warp col {0,32,64,96}

    float acc[4][4][4];
#pragma unroll
    for (int mt = 0; mt < 4; mt++)
#pragma unroll
        for (int nt = 0; nt < 4; nt++)
#pragma unroll
            for (int q = 0; q < 4; q++) acc[mt][nt][q] = 0.f;

    const int ia0 = tid * 2;
    const int ar = ia0 >> 2, ac8 = ia0 & 3;        // A: 128 rows x 4 (8-elem) cols
    const int brr = ia0 >> 4, bc8 = ia0 & 15;      // B: 32 rows x 16 cols

    uint32_t sA = s2u(&As[0][0]);
    uint32_t sB = s2u(&Bs[0][0]);

    auto issue = [&](int it) {
        const int s = it & 1;
        uint32_t a0 = sA + (uint32_t)s * (128*40*2) + ar*80 + ac8*16;
        uint32_t b0a = sB + (uint32_t)s * (32*136*2) + brr*272 + bc8*16;
        const __nv_bfloat16* ga = A  + (size_t)(m0 + ar)*K + it*32 + ac8*8;
        const __nv_bfloat16* gb = Bm + (size_t)(it*32 + brr)*N + n0 + bc8*8;
        cpa16(a0,        ga);
        cpa16(a0 + 16,   ga + 8);                  // (ar, ac8+1)
        cpa16(b0a,       gb);
        cpa16(b0a + 16,  gb + 8);                  // (brr, bc8+1)
    };

    const int NK = K / 32;
    issue(0);
    asm volatile("cp.async.commit_group;");

    for (int it = 0; it < NK; ++it) {
        __syncthreads();                 // buffer (it+1)&1 free for overwrite
        if (it + 1 < NK) issue(it + 1);
        asm volatile("cp.async.commit_group;");
        asm volatile("cp.async.wait_group 1;");    // group `it` landed
        __syncthreads();
        const int s = it & 1;
        const __nv_bfloat16* as = &As[s][0];
        const __nv_bfloat16* bs = &Bs[s][0];
#pragma unroll
        for (int ks = 0; ks < 2; ks++) {
            uint32_t af[4][4], bf[4][2];
#pragma unroll
            for (int mt = 0; mt < 4; mt++) {
                uint32_t addr = s2u(as + (wm0 + mt*16 + (lane & 15))*40 + ks*16 + (lane >> 4)*8);
                asm volatile("ldmatrix.sync.aligned.m8n8.x4.shared.b16 {%0,%1,%2,%3}, [%4];"
                    : "=r"(af[mt][0]), "=r"(af[mt][1]), "=r"(af[mt][2]), "=r"(af[mt][3])
                    : "r"(addr));
            }
#pragma unroll
            for (int nt = 0; nt < 4; nt++) {
                uint32_t addr = s2u(bs + (ks*16 + (lane & 15))*136 + wn0 + nt*8);
                asm volatile("ldmatrix.sync.aligned.m8n8.x2.trans.shared.b16 {%0,%1}, [%2];"
                    : "=r"(bf[nt][0]), "=r"(bf[nt][1]) : "r"(addr));
            }
#pragma unroll
            for (int mt = 0; mt < 4; mt++)
#pragma unroll
                for (int nt = 0; nt < 4; nt++)
                    mma16816(acc[mt][nt], af[mt], bf[nt]);
        }
    }

    // epilogue: c0,c1 -> (row L/4, col 2*(L%4)+{0,1}); c2,c3 -> row+8
#pragma unroll
    for (int mt = 0; mt < 4; mt++)
#pragma unroll
        for (int nt = 0; nt < 4; nt++) {
            int r  = m0 + wm0 + mt*16 + (lane >> 2);
            int cc = n0 + wn0 + nt*8 + (lane & 3)*2;
            float bv0 = bias ? bias[cc]   : 0.f;
            float bv1 = bias ? bias[cc+1] : 0.f;
            *(float2*)(C + (size_t)r*N + cc) =
                make_float2(acc[mt][nt][0] + bv0, acc[mt][nt][1] + bv1);
            *(float2*)(C + (size_t)(r + 8)*N + cc) =
                make_float2(acc[mt][nt][2] + bv0, acc[mt][nt][3] + bv1);
        }
}

// ---------------- fp32 SGEMM (ctx / Wc stages) ----------------
template<int ACAT, int DOTANH>
__global__ void __launch_bounds__(256) k_sgemm(
    const float* __restrict__ A, const float* __restrict__ A2,
    const float* __restrict__ Bm, const float* __restrict__ bias,
    float* __restrict__ C, int M, int N, int K,
    long long sA, long long sB, long long sC)
{
    __shared__ __align__(16) float As[8][128];
    __shared__ __align__(16) float Bs[8][128];
    A  += (long long)blockIdx.z * sA;
    Bm += (long long)blockIdx.z * sB;
    C  += (long long)blockIdx.z * sC;
    const int tid = threadIdx.x;
    const int m0 = blockIdx.y * 128, n0 = blockIdx.x * 128;
    const int ar = tid >> 1,  ac = (tid & 1) * 4;
    const int br = tid >> 5,  bc = (tid & 31) * 4;
    const int tx = tid & 15,  ty = tid >> 4;

    float acc[8][8];
#pragma unroll
    for (int i = 0; i < 8; i++)
#pragma unroll
        for (int j = 0; j < 8; j++) acc[i][j] = 0.f;

    for (int k0 = 0; k0 < K; k0 += 8) {
        float4 av;
        if (ACAT) {
            int kk = k0 + ac;
            const float* src = (kk < 512) ? (A  + (size_t)(m0+ar)*512 + kk)
                                          : (A2 + (size_t)(m0+ar)*512 + (kk-512));
            av = *(const float4*)src;
        } else {
            av = *(const float4*)(A + (size_t)(m0+ar)*K + (k0+ac));
        }
        float4 bv = *(const float4*)(Bm + (size_t)(k0+br)*N + (n0+bc));
        __syncthreads();
        As[ac+0][ar] = av.x; As[ac+1][ar] = av.y;
        As[ac+2][ar] = av.z; As[ac+3][ar] = av.w;
        *(float4*)&Bs[br][bc] = bv;
        __syncthreads();
#pragma unroll
        for (int k = 0; k < 8; k++) {
            float ra[8], rb[8];
            *(float4*)&ra[0] = *(const float4*)&As[k][ty*8];
            *(float4*)&ra[4] = *(const float4*)&As[k][ty*8+4];
            *(float4*)&rb[0] = *(const float4*)&Bs[k][tx*8];
            *(float4*)&rb[4] = *(const float4*)&Bs[k][tx*8+4];
#pragma unroll
            for (int i = 0; i < 8; i++)
#pragma unroll
                for (int j = 0; j < 8; j++) acc[i][j] += ra[i]*rb[j];
        }
    }
#pragma unroll
    for (int i = 0; i < 8; i++) {
        float* cp = C + (size_t)(m0 + ty*8 + i)*N + n0 + tx*8;
        float v[8];
#pragma unroll
        for (int j = 0; j < 8; j++) {
            float x = acc[i][j];
            if (bias) x += bias[n0 + tx*8 + j];
            if (DOTANH) x = tanhf(x);
            v[j] = x;
        }
        *(float4*)(cp+0) = make_float4(v[0],v[1],v[2],v[3]);
        *(float4*)(cp+4) = make_float4(v[4],v[5],v[6],v[7]);
    }
}

// ---------------- persistent LSTM ----------------
__device__ __forceinline__ float sigf(float x){ return 1.f/(1.f+expf(-x)); }

__device__ __forceinline__ void lstm_gemm(
    const float* __restrict__ W0, const float* __restrict__ W1,
    const float* __restrict__ x0T, const float* __restrict__ x1T,
    const float* __restrict__ addv, int addstride,
    const float* __restrict__ bias,
    float* __restrict__ gout, int K, float* red)
{
    const int tid = threadIdx.x;
    const int cl = tid & 15, kc = tid >> 4;
    const int col = blockIdx.x * 16 + cl;
    const int CH  = K >> 4;
    const int k0  = kc * CH;
    const float* Wb = ((k0 < 512) ? (W0 + (size_t)k0*G4)
                                  : (W1 + (size_t)(k0-512)*G4)) + col;
    const float* xb = (k0 < 512) ? (x0T + k0*BB) : (x1T + (k0-512)*BB);

    float acc[16];
#pragma unroll
    for (int b = 0; b < 16; b++) acc[b] = 0.f;

#pragma unroll 8
    for (int kk = 0; kk < CH; ++kk) {
        float w = Wb[(size_t)kk*G4];
        float4 xa = __ldcg((const float4*)(xb + kk*BB + 0));
        float4 xc = __ldcg((const float4*)(xb + kk*BB + 4));
        float4 xe = __ldcg((const float4*)(xb + kk*BB + 8));
        float4 xg = __ldcg((const float4*)(xb + kk*BB + 12));
        acc[0]  += w*xa.x; acc[1]  += w*xa.y; acc[2]  += w*xa.z; acc[3]  += w*xa.w;
        acc[4]  += w*xc.x; acc[5]  += w*xc.y; acc[6]  += w*xc.z; acc[7]  += w*xc.w;
        acc[8]  += w*xe.x; acc[9]  += w*xe.y; acc[10] += w*xe.z; acc[11] += w*xe.w;
        acc[12] += w*xg.x; acc[13] += w*xg.y; acc[14] += w*xg.z; acc[15] += w*xg.w;
    }
    float* r = red + cl*260 + kc*16;
    *(float4*)(r+0)  = make_float4(acc[0], acc[1], acc[2], acc[3]);
    *(float4*)(r+4)  = make_float4(acc[4], acc[5], acc[6], acc[7]);
    *(float4*)(r+8)  = make_float4(acc[8], acc[9], acc[10],acc[11]);
    *(float4*)(r+12) = make_float4(acc[12],acc[13],acc[14],acc[15]);
    __syncthreads();
    {
        const int ob = tid >> 4, ocl = tid & 15;
        float s = 0.f;
#pragma unroll
        for (int q = 0; q < 16; q++) s += red[ocl*260 + q*16 + ob];
        const int ocol = blockIdx.x*16 + ocl;
        if (bias) s += bias[ocol];
        if (addv) s += addv[(size_t)ob*addstride + ocol];
        gout[ob*G4 + ocol] = s;
    }
    __syncthreads();
}

__device__ __forceinline__ void lstm_cell(
    const float* __restrict__ g, float* __restrict__ c,
    float* __restrict__ hT, float* __restrict__ hout, int t)
{
    int gid = blockIdx.x * blockDim.x + threadIdx.x;
    if (gid < BB*HH) {
        int b = gid >> 9, j = gid & 511;
        const float* gb = g + b*G4;
        float gi = __ldcg(gb + j);
        float gf = __ldcg(gb + 512  + j);
        float gg = __ldcg(gb + 1024 + j);
        float go = __ldcg(gb + 1536 + j);
        float cc = __ldcg(c + b*HH + j);
        float cn = sigf(gf)*cc + sigf(gi)*tanhf(gg);
        float hn = sigf(go)*tanhf(cn);
        c[b*HH + j] = cn;
        hT[j*BB + b] = hn;
        if (hout) hout[(size_t)(b*TT + t)*HH + j] = hn;
    }
}

__global__ void __launch_bounds__(256, 1) k_lstm(
    const float* __restrict__ Whh0, const float* __restrict__ Wih1,
    const float* __restrict__ Whh1, const float* __restrict__ b1)
{
    __shared__ __align__(16) float red[16*260];
    int gid = blockIdx.x*256 + threadIdx.x;
    for (int i = gid; i < BB*HH; i += gridDim.x*blockDim.x) {
        g_h0T[i] = 0.f; g_h1T[i] = 0.f; g_c0[i] = 0.f; g_c1[i] = 0.f;
    }
    grid_barrier();
    for (int t = 0; t < TT; ++t) {
        lstm_gemm(Whh0, nullptr, g_h0T, nullptr,
                  g_X0 + (size_t)t*G4, TT*G4, nullptr, g_gate0, 512, red);
        grid_barrier();
        lstm_cell(g_gate0, g_c0, g_h0T, nullptr, t);
        grid_barrier();
        lstm_gemm(Wih1, Whh1, g_h0T, g_h1T, nullptr, 0, b1, g_gate1, 1024, red);
        grid_barrier();
        lstm_cell(g_gate1, g_c1, g_h1T, g_hout, t);
    }
}

// ---------------- attention ----------------
__global__ void __launch_bounds__(256) k_scores(const float* __restrict__ out) {
    __shared__ __align__(16) float As[16][64];
    __shared__ __align__(16) float Bs[16][64];
    const int b = blockIdx.z;
    const float* A = out + (size_t)b*TT*HH;
    const int m0 = blockIdx.y*64, n0 = blockIdx.x*64;
    const int tid = threadIdx.x;
    const int lr = tid >> 2, lk = (tid & 3)*4;
    const int tx = tid & 15, ty = tid >> 4;
    float acc[4][4];
#pragma unroll
    for (int i=0;i<4;i++)
#pragma unroll
        for (int j=0;j<4;j++) acc[i][j]=0.f;

    for (int k0 = 0; k0 < HH; k0 += 16) {
        float4 av = *(const float4*)(A + (size_t)(m0+lr)*HH + k0+lk);
        float4 bv = *(const float4*)(A + (size_t)(n0+lr)*HH + k0+lk);
        __syncthreads();
        As[lk+0][lr]=av.x; As[lk+1][lr]=av.y; As[lk+2][lr]=av.z; As[lk+3][lr]=av.w;
        Bs[lk+0][lr]=bv.x; Bs[lk+1][lr]=bv.y; Bs[lk+2][lr]=bv.z; Bs[lk+3][lr]=bv.w;
        __syncthreads();
#pragma unroll
        for (int k = 0; k < 16; k++) {
            float4 ra = *(const float4*)&As[k][ty*4];
            float4 rb = *(const float4*)&Bs[k][tx*4];
            float a4[4]={ra.x,ra.y,ra.z,ra.w};
            float b4[4]={rb.x,rb.y,rb.z,rb.w};
#pragma unroll
            for (int i=0;i<4;i++)
#pragma unroll
                for (int j=0;j<4;j++) acc[i][j] += a4[i]*b4[j];
        }
    }
#pragma unroll
    for (int i = 0; i < 4; i++)
        *(float4*)(g_scores + (size_t)b*TT*TT + (size_t)(m0+ty*4+i)*TT + n0 + tx*4)
            = make_float4(acc[i][0],acc[i][1],acc[i][2],acc[i][3]);
}

__global__ void k_softmax(const int* __restrict__ tok) {
    const int b = blockIdx.y, j = blockIdx.x, i = threadIdx.x;
    const float* row = g_scores + ((size_t)b*TT + j)*TT;
    const bool m = tok[b*SS + i + 1] != 0;
    float s = m ? row[i] : -1e9f;
    __shared__ float sh[8];
    float v = s;
#pragma unroll
    for (int o = 16; o; o >>= 1) v = fmaxf(v, __shfl_xor_sync(~0u, v, o));
    if ((i & 31) == 0) sh[i >> 5] = v;
    __syncthreads();
    float mx = sh[0];
#pragma unroll
    for (int q = 1; q < 8; q++) mx = fmaxf(mx, sh[q]);
    float e = expf(s - mx);
    float t2 = e;
#pragma unroll
    for (int o = 16; o; o >>= 1) t2 += __shfl_xor_sync(~0u, t2, o);
    __syncthreads();
    if ((i & 31) == 0) sh[i >> 5] = t2;
    __syncthreads();
    float sum = 0.f;
#pragma unroll
    for (int q = 0; q < 8; q++) sum += sh[q];
    g_attw[((size_t)b*TT + j)*TT + i] = m ? (e/sum) : 0.f;
}

// ---------------- launch ----------------
extern "C" void kernel_launch(void* const* d_in, const int* in_sizes, int n_in,
                              void* d_out, int out_size) {
    const int*   tok  = (const int*)  d_in[0];
    const float* emb  = (const float*)d_in[1];
    const float* Wih0 = (const float*)d_in[2];
    const float* Whh0 = (const float*)d_in[3];
    const float* b0   = (const float*)d_in[4];
    const float* Wih1 = (const float*)d_in[5];
    const float* Whh1 = (const float*)d_in[6];
    const float* b1   = (const float*)d_in[7];
    const float* Wc   = (const float*)d_in[8];
    const float* bc   = (const float*)d_in[9];
    const float* Wp   = (const float*)d_in[10];
    const float* bp   = (const float*)d_in[11];
    float* logits = (float*)d_out;

    void *p_seq, *p_X0, *p_hout, *p_attw, *p_ctx, *p_pred, *p_Abf, *p_Bbf;
    cudaGetSymbolAddress(&p_seq,  g_seq);
    cudaGetSymbolAddress(&p_X0,   g_X0);
    cudaGetSymbolAddress(&p_hout, g_hout);
    cudaGetSymbolAddress(&p_attw, g_attw);
    cudaGetSymbolAddress(&p_ctx,  g_ctx);
    cudaGetSymbolAddress(&p_pred, g_pred);
    cudaGetSymbolAddress(&p_Abf,  g_Abf);
    cudaGetSymbolAddress(&p_Bbf,  g_Bbf);
    float* seq  = (float*)p_seq;   float* X0   = (float*)p_X0;
    float* hout = (float*)p_hout;  float* attw = (float*)p_attw;
    float* ctx  = (float*)p_ctx;   float* pred = (float*)p_pred;
    __nv_bfloat16* Abf = (__nv_bfloat16*)p_Abf;
    __nv_bfloat16* Bbf = (__nv_bfloat16*)p_Bbf;

    // 1. embedding gather
    k_gather<<<NROW, 128>>>(tok, emb, seq);
    // 2. X0 = seq @ Wih0 + b0 via split-bf16 HMMA
    k_cvtA<<<(NROW*HH/4)/256, 256>>>(seq, Abf);
    k_cvtB<<<(HH*G4/4)/256, 256>>>(Wih0, Bbf, G4);
    k_hgemm<<<dim3(G4/128, NROW/128), 256>>>(Abf, Bbf, b0, X0, NROW, G4, KS);
    // 3. persistent 2-layer LSTM (128 co-resident CTAs)
    k_lstm<<<128, 256>>>(Whh0, Wih1, Whh1, b1);
    // 4. scores_b = out_b @ out_b^T
    k_scores<<<dim3(TT/64, TT/64, BB), 256>>>(hout);
    // 5. masked softmax (axis=1 via symmetry) -> attw = w^T
    k_softmax<<<dim3(TT, BB, 1), TT>>>(tok);
    // 6. ctx_b = attw_b @ out_b   (batched, fp32)
    k_sgemm<0,0><<<dim3(HH/128, TT/128, BB), 256>>>(
        attw, nullptr, hout, nullptr, ctx, TT, HH, TT,
        (long long)TT*TT, (long long)TT*HH, (long long)TT*HH);
    // 7. pred = tanh([ctx | out] @ Wc + bc)   (fp32)
    k_sgemm<1,1><<<dim3(HH/128, NROW/128, 1), 256>>>(
        ctx, hout, Wc, bc, pred, NROW, HH, 2*HH, 0, 0, 0);
    // 8. logits = pred @ Wp + bp via split-bf16 HMMA
    k_cvtA<<<(NROW*HH/4)/256, 256>>>(pred, Abf);
    k_cvtB<<<(HH*VV/4)/256, 256>>>(Wp, Bbf, VV);
    k_hgemm<<<dim3(VV/128, NROW/128), 256>>>(Abf, Bbf, bp, logits, NROW, VV, KS);
}